// round 11
// baseline (speedup 1.0000x reference)
#include <cuda_runtime.h>
#include <cuda_bf16.h>

#define CB 2
#define CH 12
#define CS 2048
#define CDM 768
#define CDK 64
#define CM (CB*CS)   /* 4096 rows */

// Scratch (no allocation allowed): Q/K/V head-major [B,H,S,64], ctx row-major [4096,768]
__device__ float g_q[CB*CH*CS*CDK];
__device__ float g_k[CB*CH*CS*CDK];
__device__ float g_v[CB*CH*CS*CDK];
__device__ float g_ctx[CM*CDM];

// ---------------------------------------------------------------------------
// Core GEMM body (128x128x16): C = A @ W^T + bias.  A:[4096,768] row-major,
// W:[N,K] row-major, K=768. 256 threads, 8x8 microtile, float4 smem access.
// Double-buffered smem (one barrier per slab) + register prefetch.
// Smem k-major: As[k][m] stride 132 (compute loads conflict-free, stores 2-way).
// #pragma unroll 2 on the k0 loop specializes the buf toggle so both smem
// base addresses become compile-time constants.
// MODE 0: scatter into head-major [B,H,S,64] ; MODE 1: row-major [4096,768].
// ---------------------------------------------------------------------------
template<int MODE>
__device__ __forceinline__
void gemm_body(const float* __restrict__ A,
               const float* __restrict__ W,
               const float* __restrict__ bias,
               float* __restrict__ C,
               float As[2][16 * 132], float Ws[2][16 * 132])
{
    const int tid = threadIdx.x;
    const int tx  = tid & 15;        // n-groups: tx*4 and 64+tx*4
    const int ty  = tid >> 4;        // m-groups: ty*4 and 64+ty*4
    const int mBase = blockIdx.y * 128;
    const int nBase = blockIdx.x * 128;

    const int lrow = tid >> 2;            // 0..63
    const int lc4  = (tid & 3) << 2;      // 0,4,8,12

    const float* Ap = A + (size_t)(mBase + lrow) * CDM + lc4;
    const float* Wp = W + (size_t)(nBase + lrow) * CDM + lc4;

    float4 pa0 = *(const float4*)Ap;
    float4 pa1 = *(const float4*)(Ap + (size_t)64 * CDM);
    float4 pw0 = *(const float4*)Wp;
    float4 pw1 = *(const float4*)(Wp + (size_t)64 * CDM);

    float acc[8][8];
    #pragma unroll
    for (int i = 0; i < 8; i++)
        #pragma unroll
        for (int j = 0; j < 8; j++) acc[i][j] = 0.f;

    {
        float* a = As[0] + lc4 * 132 + lrow;
        a[0] = pa0.x; a[132] = pa0.y; a[264] = pa0.z; a[396] = pa0.w;
        float* a2 = a + 64;
        a2[0] = pa1.x; a2[132] = pa1.y; a2[264] = pa1.z; a2[396] = pa1.w;
        float* w = Ws[0] + lc4 * 132 + lrow;
        w[0] = pw0.x; w[132] = pw0.y; w[264] = pw0.z; w[396] = pw0.w;
        float* w2 = w + 64;
        w2[0] = pw1.x; w2[132] = pw1.y; w2[264] = pw1.z; w2[396] = pw1.w;
    }
    __syncthreads();

    int buf = 0;
    #pragma unroll 2
    for (int k0 = 0; k0 < CDM; k0 += 16) {
        const int kn = k0 + 16;
        const bool more = (kn < CDM);
        if (more) {   // prefetch next slab into registers while computing
            pa0 = *(const float4*)(Ap + kn);
            pa1 = *(const float4*)(Ap + (size_t)64 * CDM + kn);
            pw0 = *(const float4*)(Wp + kn);
            pw1 = *(const float4*)(Wp + (size_t)64 * CDM + kn);
        }

        const float* Ab = As[buf];
        const float* Wb = Ws[buf];
        #pragma unroll
        for (int kk = 0; kk < 16; kk++) {
            float4 a0 = *(const float4*)(Ab + kk * 132 + ty * 4);
            float4 a1 = *(const float4*)(Ab + kk * 132 + 64 + ty * 4);
            float4 w0 = *(const float4*)(Wb + kk * 132 + tx * 4);
            float4 w1 = *(const float4*)(Wb + kk * 132 + 64 + tx * 4);
            float av[8] = {a0.x, a0.y, a0.z, a0.w, a1.x, a1.y, a1.z, a1.w};
            float wv[8] = {w0.x, w0.y, w0.z, w0.w, w1.x, w1.y, w1.z, w1.w};
            #pragma unroll
            for (int i = 0; i < 8; i++)
                #pragma unroll
                for (int j = 0; j < 8; j++)
                    acc[i][j] += av[i] * wv[j];
        }

        if (more) {
            // other buffer's last readers finished before the previous barrier
            float* a = As[buf ^ 1] + lc4 * 132 + lrow;
            a[0] = pa0.x; a[132] = pa0.y; a[264] = pa0.z; a[396] = pa0.w;
            float* a2 = a + 64;
            a2[0] = pa1.x; a2[132] = pa1.y; a2[264] = pa1.z; a2[396] = pa1.w;
            float* w = Ws[buf ^ 1] + lc4 * 132 + lrow;
            w[0] = pw0.x; w[132] = pw0.y; w[264] = pw0.z; w[396] = pw0.w;
            float* w2 = w + 64;
            w2[0] = pw1.x; w2[132] = pw1.y; w2[264] = pw1.z; w2[396] = pw1.w;
            __syncthreads();
            buf ^= 1;
        }
    }

    float bv[8];
    #pragma unroll
    for (int j = 0; j < 8; j++)
        bv[j] = bias[nBase + ((j < 4) ? (tx * 4 + j) : (64 + tx * 4 + j - 4))];

    #pragma unroll
    for (int i = 0; i < 8; i++) {
        const int m = mBase + ((i < 4) ? (ty * 4 + i) : (64 + ty * 4 + i - 4));
        float4 o0 = make_float4(acc[i][0] + bv[0], acc[i][1] + bv[1],
                                acc[i][2] + bv[2], acc[i][3] + bv[3]);
        float4 o1 = make_float4(acc[i][4] + bv[4], acc[i][5] + bv[5],
                                acc[i][6] + bv[6], acc[i][7] + bv[7]);
        if (MODE == 0) {
            const int bb = m >> 11, s = m & (CS - 1);
            const int n0 = nBase + tx * 4;
            const int n1 = nBase + 64 + tx * 4;
            *(float4*)&C[(((size_t)bb * CH + (n0 >> 6)) * CS + s) * CDK + (n0 & 63)] = o0;
            *(float4*)&C[(((size_t)bb * CH + (n1 >> 6)) * CS + s) * CDK + (n1 & 63)] = o1;
        } else {
            *(float4*)&C[(size_t)m * CDM + nBase + tx * 4] = o0;
            *(float4*)&C[(size_t)m * CDM + nBase + 64 + tx * 4] = o1;
        }
    }
}

// Fused Q/K/V projections: blockIdx.z selects the projection. One launch of
// 576 CTAs (2 full waves at 2 CTA/SM) instead of three 192-CTA partial waves.
__global__ __launch_bounds__(256)
void gemm_qkv(const float* __restrict__ q,  const float* __restrict__ k,
              const float* __restrict__ v,
              const float* __restrict__ Wq, const float* __restrict__ bq,
              const float* __restrict__ Wk, const float* __restrict__ bk,
              const float* __restrict__ Wv, const float* __restrict__ bv)
{
    __shared__ float As[2][16 * 132];
    __shared__ float Ws[2][16 * 132];
    const int z = blockIdx.z;
    const float* A    = (z == 0) ? q  : (z == 1) ? k  : v;
    const float* W    = (z == 0) ? Wq : (z == 1) ? Wk : Wv;
    const float* bias = (z == 0) ? bq : (z == 1) ? bk : bv;
    float*       C    = (z == 0) ? g_q : (z == 1) ? g_k : g_v;
    gemm_body<0>(A, W, bias, C, As, Ws);
}

// ---------------------------------------------------------------------------
// Output projection, 128x64x16 tiles: 384 CTAs -> single wave at 3 CTA/SM
// (the 128x128 version left 35% of the chip idle on its 192-CTA grid).
// __launch_bounds__(256,3) makes the 3-CTA/SM occupancy a compiler contract
// (84-reg cap); without it, ptxas padding past 84 regs would silently halve
// occupancy and re-create the two-wave underfill this kernel exists to avoid.
// 8x4 microtile, W tile stride 68 (compute loads conflict-free per phase).
// ---------------------------------------------------------------------------
__global__ __launch_bounds__(256, 3)
void gemm_out(const float* __restrict__ Wo, const float* __restrict__ bo,
              float* __restrict__ C)
{
    __shared__ float As[2][16 * 132];
    __shared__ float Ws[2][16 * 68];

    const float* A = g_ctx;
    const int tid = threadIdx.x;
    const int tx  = tid & 15;        // n: tx*4 .. tx*4+3
    const int ty  = tid >> 4;        // m-groups: ty*4 and 64+ty*4
    const int mBase = blockIdx.y * 128;
    const int nBase = blockIdx.x * 64;

    const int lrow = tid >> 2;            // 0..63
    const int lc4  = (tid & 3) << 2;      // 0,4,8,12

    const float* Ap = A  + (size_t)(mBase + lrow) * CDM + lc4;
    const float* Wp = Wo + (size_t)(nBase + lrow) * CDM + lc4;

    float4 pa0 = *(const float4*)Ap;
    float4 pa1 = *(const float4*)(Ap + (size_t)64 * CDM);
    float4 pw0 = *(const float4*)Wp;

    float acc[8][4];
    #pragma unroll
    for (int i = 0; i < 8; i++)
        #pragma unroll
        for (int j = 0; j < 4; j++) acc[i][j] = 0.f;

    {
        float* a = As[0] + lc4 * 132 + lrow;
        a[0] = pa0.x; a[132] = pa0.y; a[264] = pa0.z; a[396] = pa0.w;
        float* a2 = a + 64;
        a2[0] = pa1.x; a2[132] = pa1.y; a2[264] = pa1.z; a2[396] = pa1.w;
        float* w = Ws[0] + lc4 * 68 + lrow;
        w[0] = pw0.x; w[68] = pw0.y; w[136] = pw0.z; w[204] = pw0.w;
    }
    __syncthreads();

    int buf = 0;
    #pragma unroll 2
    for (int k0 = 0; k0 < CDM; k0 += 16) {
        const int kn = k0 + 16;
        const bool more = (kn < CDM);
        if (more) {
            pa0 = *(const float4*)(Ap + kn);
            pa1 = *(const float4*)(Ap + (size_t)64 * CDM + kn);
            pw0 = *(const float4*)(Wp + kn);
        }

        const float* Ab = As[buf];
        const float* Wb = Ws[buf];
        #pragma unroll
        for (int kk = 0; kk < 16; kk++) {
            float4 a0 = *(const float4*)(Ab + kk * 132 + ty * 4);
            float4 a1 = *(const float4*)(Ab + kk * 132 + 64 + ty * 4);
            float4 w0 = *(const float4*)(Wb + kk * 68 + tx * 4);
            float av[8] = {a0.x, a0.y, a0.z, a0.w, a1.x, a1.y, a1.z, a1.w};
            float wv[4] = {w0.x, w0.y, w0.z, w0.w};
            #pragma unroll
            for (int i = 0; i < 8; i++)
                #pragma unroll
                for (int j = 0; j < 4; j++)
                    acc[i][j] += av[i] * wv[j];
        }

        if (more) {
            float* a = As[buf ^ 1] + lc4 * 132 + lrow;
            a[0] = pa0.x; a[132] = pa0.y; a[264] = pa0.z; a[396] = pa0.w;
            float* a2 = a + 64;
            a2[0] = pa1.x; a2[132] = pa1.y; a2[264] = pa1.z; a2[396] = pa1.w;
            float* w = Ws[buf ^ 1] + lc4 * 68 + lrow;
            w[0] = pw0.x; w[68] = pw0.y; w[136] = pw0.z; w[204] = pw0.w;
            __syncthreads();
            buf ^= 1;
        }
    }

    float bv[4];
    #pragma unroll
    for (int j = 0; j < 4; j++) bv[j] = bo[nBase + tx * 4 + j];

    #pragma unroll
    for (int i = 0; i < 8; i++) {
        const int m = mBase + ((i < 4) ? (ty * 4 + i) : (64 + ty * 4 + i - 4));
        float4 o0 = make_float4(acc[i][0] + bv[0], acc[i][1] + bv[1],
                                acc[i][2] + bv[2], acc[i][3] + bv[3]);
        *(float4*)&C[(size_t)m * CDM + nBase + tx * 4] = o0;
    }
}

// ---------------------------------------------------------------------------
// Flash attention, causal, key-position time-decay bias exp(-(c+1)).
// One CTA per (b, h, 64-query tile); qt = 31 - blockIdx.x (heavy tiles first).
// 256 threads = 16(tx) x 16(ty); thread owns rows ty*4+i, cols tx*4+j.
// Q,K transposed [d][s] with XOR-chunk swizzle (float4 loads conflict-free).
// P ALIASES the K tile (K is dead after QK; a barrier separates last K read
// from first P write). P stores are packed STS.128 (conflict-free).
// K/V tile loads are front-batched in two 4-LDG.128 groups (guaranteed MLP=4
// in SASS) so the post-barrier load phase exposes ~1/4 the L2 latency.
// V [c][n] stride 68. Smem 49 KB -> 4 CTAs/SM.
// Bias note: exp(-(c+1)) == 0.0f in fp32 for c+1 >= 104 (below min subnormal),
// so the bias block is skipped for key tiles with kBase >= 128 — identical
// arithmetic to the reference, which underflows the same way.
// ---------------------------------------------------------------------------
__global__ __launch_bounds__(256, 4)
void attn_kernel()
{
    extern __shared__ float sm[];
    float* QsT = sm;                 // 64*64 swizzled [d][q]
    float* KsT = sm + 4096;          // 64*64 swizzled [d][k]; P reuses this
    float* Ps  = KsT;                // alias: P tile [c][q], same swizzle
    float* Vs  = sm + 8192;          // 64*68 [c][n]

    const int tid = threadIdx.x;
    const int tx  = tid & 15;
    const int ty  = tid >> 4;
    const int qt  = (CS / 64 - 1) - blockIdx.x;   // descending: 31..0
    const int h   = blockIdx.y;
    const int b   = blockIdx.z;
    const int qBase = qt * 64;

    const size_t headOff = ((size_t)b * CH + h) * (size_t)CS * CDK;
    const float* Qg = g_q + headOff;
    const float* Kg = g_k + headOff;
    const float* Vg = g_v + headOff;

    // Per-thread load coords (reused every tile)
    const int lr = tid >> 4;              // 0..15 base row
    const int lc = (tid & 15) << 2;       // d base 0..60

    // Load Q tile transposed + swizzled. phys chunk = (r>>2)^(d>>2)
    #pragma unroll
    for (int t = 0; t < 4; t++) {
        int r = lr + t * 16;
        float4 v = *(const float4*)(Qg + (size_t)(qBase + r) * CDK + lc);
        int base = (((r >> 2) ^ (lc >> 2)) << 2) + (r & 3);
        QsT[(lc + 0) * 64 + base] = v.x;
        QsT[(lc + 1) * 64 + base] = v.y;
        QsT[(lc + 2) * 64 + base] = v.z;
        QsT[(lc + 3) * 64 + base] = v.w;
    }

    float o[4][4];
    float mi[4], li[4];
    #pragma unroll
    for (int i = 0; i < 4; i++) {
        mi[i] = -1e30f; li[i] = 0.f;
        #pragma unroll
        for (int j = 0; j < 4; j++) o[i][j] = 0.f;
    }

    for (int kt = 0; kt <= qt; kt++) {
        __syncthreads();   // prev iter done reading Ps(=KsT)/Vs; Q stores iter 0
        const int kBase = kt * 64;

        // Front-batched loads: group 1 = K rows (4x LDG.128), then stores;
        // group 2 = V rows. Pure reordering of the old interleaved loop.
        {
            float4 kv0, kv1, kv2, kv3;
            const float* Kp = Kg + (size_t)(kBase + lr) * CDK + lc;
            kv0 = *(const float4*)(Kp);
            kv1 = *(const float4*)(Kp + (size_t)16 * CDK);
            kv2 = *(const float4*)(Kp + (size_t)32 * CDK);
            kv3 = *(const float4*)(Kp + (size_t)48 * CDK);
            #pragma unroll
            for (int t = 0; t < 4; t++) {
                int r = lr + t * 16;
                float4 kv = (t == 0) ? kv0 : (t == 1) ? kv1 : (t == 2) ? kv2 : kv3;
                int base = (((r >> 2) ^ (lc >> 2)) << 2) + (r & 3);
                KsT[(lc + 0) * 64 + base] = kv.x;
                KsT[(lc + 1) * 64 + base] = kv.y;
                KsT[(lc + 2) * 64 + base] = kv.z;
                KsT[(lc + 3) * 64 + base] = kv.w;
            }
            float4 vv0, vv1, vv2, vv3;
            const float* Vp = Vg + (size_t)(kBase + lr) * CDK + lc;
            vv0 = *(const float4*)(Vp);
            vv1 = *(const float4*)(Vp + (size_t)16 * CDK);
            vv2 = *(const float4*)(Vp + (size_t)32 * CDK);
            vv3 = *(const float4*)(Vp + (size_t)48 * CDK);
            *(float4*)&Vs[(lr +  0) * 68 + lc] = vv0;
            *(float4*)&Vs[(lr + 16) * 68 + lc] = vv1;
            *(float4*)&Vs[(lr + 32) * 68 + lc] = vv2;
            *(float4*)&Vs[(lr + 48) * 68 + lc] = vv3;
        }
        __syncthreads();

        // S = Q K^T
        float s[4][4];
        #pragma unroll
        for (int i = 0; i < 4; i++)
            #pragma unroll
            for (int j = 0; j < 4; j++) s[i][j] = 0.f;

        #pragma unroll 16
        for (int d = 0; d < 64; d++) {
            const int sw = (d >> 2) & 15;
            float4 q4 = *(const float4*)&QsT[d * 64 + ((ty ^ sw) << 2)];
            float4 k4 = *(const float4*)&KsT[d * 64 + ((tx ^ sw) << 2)];
            float qa[4] = {q4.x, q4.y, q4.z, q4.w};
            float ka[4] = {k4.x, k4.y, k4.z, k4.w};
            #pragma unroll
            for (int i = 0; i < 4; i++)
                #pragma unroll
                for (int j = 0; j < 4; j++)
                    s[i][j] += qa[i] * ka[j];
        }

        // scale + time-decay bias + causal mask (only diagonal tile masks).
        // Bias underflows to exactly 0 for kBase >= 128 -> skip the MUFU work.
        const bool diag = (kt == qt);
        if (kBase < 128) {
            #pragma unroll
            for (int j = 0; j < 4; j++) {
                const int cl = tx * 4 + j;
                const float tb = __expf(-(float)(kBase + cl + 1));
                #pragma unroll
                for (int i = 0; i < 4; i++)
                    s[i][j] = s[i][j] * 0.125f - tb;
            }
        } else {
            #pragma unroll
            for (int j = 0; j < 4; j++)
                #pragma unroll
                for (int i = 0; i < 4; i++)
                    s[i][j] *= 0.125f;
        }
        if (diag) {
            #pragma unroll
            for (int j = 0; j < 4; j++) {
                const int cl = tx * 4 + j;
                #pragma unroll
                for (int i = 0; i < 4; i++)
                    if (cl > ty * 4 + i) s[i][j] = -1e9f;
            }
        }

        // online softmax per row, register-only (reduce across 16-lane tx group)
        #pragma unroll
        for (int i = 0; i < 4; i++) {
            float mt = fmaxf(fmaxf(s[i][0], s[i][1]), fmaxf(s[i][2], s[i][3]));
            #pragma unroll
            for (int msk = 1; msk < 16; msk <<= 1)
                mt = fmaxf(mt, __shfl_xor_sync(0xffffffffu, mt, msk));

            const float mnew  = fmaxf(mi[i], mt);
            const float scale = __expf(mi[i] - mnew);
            float rs = 0.f;
            #pragma unroll
            for (int j = 0; j < 4; j++) {
                float p = __expf(s[i][j] - mnew);
                s[i][j] = p;
                rs += p;
            }
            #pragma unroll
            for (int msk = 1; msk < 16; msk <<= 1)
                rs += __shfl_xor_sync(0xffffffffu, rs, msk);

            li[i] = li[i] * scale + rs;
            mi[i] = mnew;
            #pragma unroll
            for (int j = 0; j < 4; j++) o[i][j] *= scale;
        }

        __syncthreads();   // all QK reads of KsT done -> safe to overwrite with P

        // P stores packed as STS.128: for fixed j the four i-values are
        // consecutive at pc+0..3 (16B-aligned). Conflict-free per 8-lane phase.
        const int pc = ((ty ^ tx) << 2);   // swizzled q-chunk (c>>2 == tx)
        #pragma unroll
        for (int j = 0; j < 4; j++)
            *(float4*)&Ps[(tx * 4 + j) * 64 + pc] =
                make_float4(s[0][j], s[1][j], s[2][j], s[3][j]);
        __syncwarp();   // P rows for this thread are produced within its own warp

        // O += P V
        #pragma unroll 16
        for (int c = 0; c < 64; c++) {
            const int sw = (c >> 2) & 15;
            float4 p4 = *(const float4*)&Ps[c * 64 + ((ty ^ sw) << 2)];
            float4 v4 = *(const float4*)&Vs[c * 68 + tx * 4];
            float pa[4] = {p4.x, p4.y, p4.z, p4.w};
            float va[4] = {v4.x, v4.y, v4.z, v4.w};
            #pragma unroll
            for (int i = 0; i < 4; i++)
                #pragma unroll
                for (int j = 0; j < 4; j++)
                    o[i][j] += pa[i] * va[j];
        }
    }

    // ctx row-major [B*S, 768], cols h*64 + tx*4 + j  (float4, coalesced).
    // __fdividef: bare MUFU.RCP; li in [1,64], well inside the safe range.
    #pragma unroll
    for (int i = 0; i < 4; i++) {
        const int r = qBase + ty * 4 + i;
        const float inv = __fdividef(1.0f, li[i]);
        float4 ov = make_float4(o[i][0] * inv, o[i][1] * inv,
                                o[i][2] * inv, o[i][3] * inv);
        *(float4*)&g_ctx[((size_t)b * CS + r) * CDM + h * CDK + tx * 4] = ov;
    }
}

// ---------------------------------------------------------------------------
extern "C" void kernel_launch(void* const* d_in, const int* in_sizes, int n_in,
                              void* d_out, int out_size)
{
    (void)in_sizes; (void)n_in; (void)out_size;
    const float* q  = (const float*)d_in[0];
    const float* k  = (const float*)d_in[1];
    const float* v  = (const float*)d_in[2];
    /* d_in[3] = mask: reference builds a tril causal mask; hard-coded. */
    const float* Wq = (const float*)d_in[4];
    const float* bq = (const float*)d_in[5];
    const float* Wk = (const float*)d_in[6];
    const float* bk = (const float*)d_in[7];
    const float* Wv = (const float*)d_in[8];
    const float* bv = (const float*)d_in[9];
    const float* Wo = (const float*)d_in[10];
    const float* bo = (const float*)d_in[11];

    const int smemAttn = (2 * 4096 + 64 * 68) * (int)sizeof(float);  // 50176 B
    cudaFuncSetAttribute(attn_kernel,
                         cudaFuncAttributeMaxDynamicSharedMemorySize, smemAttn);

    gemm_qkv<<<dim3(CDM / 128, CM / 128, 3), 256>>>(q, k, v, Wq, bq, Wk, bk, Wv, bv);

    attn_kernel<<<dim3(CS / 64, CH, CB), 256, smemAttn>>>();

    gemm_out<<<dim3(CDM / 64, CM / 128), 256>>>(Wo, bo, (float*)d_out);
}